// round 5
// baseline (speedup 1.0000x reference)
#include <cuda_runtime.h>
#include <math.h>
#include <float.h>

#define BATCH 8
#define HIDC  256
#define ZCH   64
#define KCODE 512

// ---------------- scratch (device globals; no allocation allowed) ----------------
__device__ float g_h1 [BATCH * HIDC * 64 * 64];  // after c1
__device__ float g_h2a[BATCH * HIDC * 32 * 32];  // ping
__device__ float g_h2b[BATCH * HIDC * 32 * 32];  // pong
__device__ float g_rr [BATCH * HIDC * 32 * 32];  // residual intermediate
__device__ float g_d1 [BATCH * HIDC * 32 * 32];  // decoder stage 1
__device__ float g_d2 [BATCH * HIDC * 64 * 64];  // decoder stage 2
__device__ float g_wt1[4 * HIDC * HIDC * 4];     // subpixel-decomposed t1 weights

// packed fp32x2 FMA (Blackwell): d = a * b + d, elementwise on 2 packed f32
__device__ __forceinline__ void fma2(unsigned long long& d,
                                     unsigned long long a,
                                     unsigned long long b)
{
    asm("fma.rn.f32x2 %0, %1, %2, %0;" : "+l"(d) : "l"(a), "l"(b));
}
__device__ __forceinline__ unsigned long long dup2(float v)
{
    unsigned long long r;
    asm("mov.b64 %0, {%1, %1};" : "=l"(r) : "f"(v));
    return r;
}

// =======================================================================
// Implicit-GEMM conv, double-buffered smem, f32x2 packed math.
//   C[M=Cout][N=B*Hout*Wout] = A[M][K] * B(gathered)[K][N]
// BN=128, BK=8 fixed. BMv/TM templated (128/8 or 64/4). 256 threads.
// __launch_bounds__(256,2): 2 CTAs/SM is mandatory to hide LDS latency +
// the per-tile barrier (round-4 lesson: 1 CTA/SM -> issue 31%).
// SUBPIX: 2x2 subpixel conv implementing convT(k4,s2,p1); blockIdx.z = parity.
// =======================================================================
template<int KH, int KW, int BMv, int TM, bool SUBPIX, bool VST>
__global__ __launch_bounds__(256, 2) void conv_gemm(
    const float* __restrict__ A, const float* __restrict__ in,
    const float* __restrict__ bias, const float* __restrict__ res,
    float* __restrict__ out,
    int Cin, int Hin, int Win, int Cout, int Hout, int Wout,
    int stride, int pad, int K, int act, int inRelu,
    int Hfull, int Wfull)
{
    constexpr int BN = 128, BK = 8, TN = 8;
    constexpr int KHW = KH * KW;
    constexpr int TP = TM / 2;                 // M-pairs per thread
    __shared__ float As[2][BK][BMv];
    __shared__ float Bs[2][BK][BN];

    const int tid = threadIdx.x;
    const int m0 = blockIdx.y * BMv;
    const int n0 = blockIdx.x * BN;
    const int HW = Hout * Wout;

    int par_y = 0, par_x = 0;
    const float* Ab = A;
    if (SUBPIX) {
        int pz = blockIdx.z;
        par_y = pz >> 1; par_x = pz & 1;
        Ab = A + (long)pz * Cout * K;
    }

    // ---- B gather mapping: fixed n per thread, 4 consecutive k ----
    const int bn = tid & (BN - 1);
    const int bk = (tid >> 7) << 2;
    const int n  = n0 + bn;
    const int bimg = n / HW;
    const int hw   = n - bimg * HW;
    const int oy   = hw / Wout;
    const int ox   = hw - oy * Wout;
    const float* inb = in + (long)bimg * Cin * Hin * Win;
    int iy0, ix0;
    if (SUBPIX) { iy0 = oy - (1 - par_y); ix0 = ox - (1 - par_x); }
    else        { iy0 = oy * stride - pad; ix0 = ox * stride - pad; }

    // ---- A load mapping: one float4 per (active) thread per tile ----
    constexpr int NA4 = BMv * BK / 4;     // 256 or 128
    const int am = tid >> 1;
    const int ak = (tid & 1) << 2;
    const bool aload = (NA4 == 256) || (tid < 128);
    const float* Arow = aload ? (Ab + (long)(m0 + am) * K + ak) : Ab;

    // ---- compute mapping ----
    const int rm = (tid & 15) * TM;
    const int rn = (tid >> 4) * TN;
    unsigned long long acc2[TP][TN];
    #pragma unroll
    for (int i = 0; i < TP; i++)
        #pragma unroll
        for (int j = 0; j < TN; j++) acc2[i][j] = 0ull;

    auto gatherB = [&](int k0, float* bv) {
        #pragma unroll
        for (int i = 0; i < 4; i++) {
            int k  = k0 + bk + i;
            int ic = k / KHW;
            int rr = k - ic * KHW;
            int ky = rr / KW;
            int kx = rr - ky * KW;
            int iy = iy0 + ky;
            int ix = ix0 + kx;
            float v = 0.f;
            if ((unsigned)iy < (unsigned)Hin && (unsigned)ix < (unsigned)Win)
                v = inb[(ic * Hin + iy) * Win + ix];
            if (inRelu) v = fmaxf(v, 0.f);
            bv[i] = v;
        }
    };

    const int nt = K / BK;
    float4 av;
    float  bv[4];

    // preload tile 0
    if (aload) av = *reinterpret_cast<const float4*>(Arow);
    gatherB(0, bv);
    if (aload) {
        As[0][ak + 0][am] = av.x; As[0][ak + 1][am] = av.y;
        As[0][ak + 2][am] = av.z; As[0][ak + 3][am] = av.w;
    }
    #pragma unroll
    for (int i = 0; i < 4; i++) Bs[0][bk + i][bn] = bv[i];
    __syncthreads();

    int cur = 0;
    for (int t = 0; t < nt; t++) {
        if (t + 1 < nt) {
            int k0n = (t + 1) * BK;
            if (aload) av = *reinterpret_cast<const float4*>(Arow + k0n);
            gatherB(k0n, bv);
        }
        #pragma unroll
        for (int kk = 0; kk < BK; kk++) {
            // A-side: TP packed pairs along M, free from 64-bit smem reads
            unsigned long long ap[TP];
            {
                ulonglong2 u0 = *reinterpret_cast<const ulonglong2*>(&As[cur][kk][rm]);
                ap[0] = u0.x; ap[1] = u0.y;
                if (TP == 4) {
                    ulonglong2 u1 = *reinterpret_cast<const ulonglong2*>(&As[cur][kk][rm + 4]);
                    ap[2] = u1.x; ap[3] = u1.y;
                }
            }
            float b[TN];
            *reinterpret_cast<float4*>(&b[0]) = *reinterpret_cast<const float4*>(&Bs[cur][kk][rn]);
            *reinterpret_cast<float4*>(&b[4]) = *reinterpret_cast<const float4*>(&Bs[cur][kk][rn + 4]);
            #pragma unroll
            for (int j = 0; j < TN; j++) {
                unsigned long long bd = dup2(b[j]);
                #pragma unroll
                for (int i = 0; i < TP; i++)
                    fma2(acc2[i][j], ap[i], bd);
            }
        }
        if (t + 1 < nt) {
            int nx = cur ^ 1;
            if (aload) {
                As[nx][ak + 0][am] = av.x; As[nx][ak + 1][am] = av.y;
                As[nx][ak + 2][am] = av.z; As[nx][ak + 3][am] = av.w;
            }
            #pragma unroll
            for (int i = 0; i < 4; i++) Bs[nx][bk + i][bn] = bv[i];
            __syncthreads();
            cur = nx;
        }
    }

    // ---- epilogue ----
    const int nb  = n0 + rn;
    const int b2  = nb / HW;                 // same image for all TN columns
    const int hwb = nb - b2 * HW;
    const int eoy = hwb / Wout;
    const int eox = hwb - eoy * Wout;        // row-constant: eox+TN-1 < Wout
    const long HWf = (long)Hfull * Wfull;
    const long base = (long)b2 * Cout * HWf;

    #pragma unroll
    for (int i = 0; i < TM; i++) {
        const int oc = m0 + rm + i;
        const float bvs = bias[oc];
        if (VST && !SUBPIX) {
            long idx = base + (long)oc * HWf + hwb;
            #pragma unroll
            for (int j = 0; j < TN; j += 4) {
                float2 p0 = *reinterpret_cast<const float2*>(&acc2[i >> 1][j + 0]);
                float2 p1 = *reinterpret_cast<const float2*>(&acc2[i >> 1][j + 1]);
                float2 p2 = *reinterpret_cast<const float2*>(&acc2[i >> 1][j + 2]);
                float2 p3 = *reinterpret_cast<const float2*>(&acc2[i >> 1][j + 3]);
                float4 v;
                v.x = ((i & 1) ? p0.y : p0.x) + bvs;
                v.y = ((i & 1) ? p1.y : p1.x) + bvs;
                v.z = ((i & 1) ? p2.y : p2.x) + bvs;
                v.w = ((i & 1) ? p3.y : p3.x) + bvs;
                if (res) {
                    float4 r = *reinterpret_cast<const float4*>(res + idx + j);
                    v.x += r.x; v.y += r.y; v.z += r.z; v.w += r.w;
                }
                if (act == 1) {
                    v.x = fmaxf(v.x, 0.f); v.y = fmaxf(v.y, 0.f);
                    v.z = fmaxf(v.z, 0.f); v.w = fmaxf(v.w, 0.f);
                }
                *reinterpret_cast<float4*>(out + idx + j) = v;
            }
        } else {
            #pragma unroll
            for (int j = 0; j < TN; j++) {
                float2 p = *reinterpret_cast<const float2*>(&acc2[i >> 1][j]);
                float v = ((i & 1) ? p.y : p.x) + bvs;
                if (act == 1) v = fmaxf(v, 0.f);
                int fy, fx;
                if (SUBPIX) { fy = 2 * eoy + par_y; fx = 2 * (eox + j) + par_x; }
                else        { fy = eoy;             fx = eox + j; }
                out[base + (long)oc * HWf + (long)fy * Wfull + fx] = v;
            }
        }
    }
}

// ---------------- VQ: one warp per z-vector ----------------
__global__ __launch_bounds__(128) void vq_kernel(
    const float* __restrict__ z, const float* __restrict__ cb,
    float* __restrict__ ek, float* __restrict__ ids_out)
{
    const int warp = threadIdx.x >> 5;
    const int lane = threadIdx.x & 31;
    const int n = blockIdx.x * 4 + warp;         // [0, 8192)
    const int b  = n >> 10;
    const int hw = n & 1023;

    __shared__ float zs[4][ZCH];
    const float* zb = z + (long)b * ZCH * 1024 + hw;
    zs[warp][lane]      = zb[(long)lane * 1024];
    zs[warp][lane + 32] = zb[(long)(lane + 32) * 1024];
    __syncwarp();

    float best = FLT_MAX;
    int bi = 0;
    for (int k = lane; k < KCODE; k += 32) {
        const float* c = cb + k * ZCH;
        float s = 0.f;
        #pragma unroll 16
        for (int ci = 0; ci < ZCH; ci++) {
            float cv = c[ci];
            s = fmaf(cv, cv - 2.f * zs[warp][ci], s);   // |c|^2 - 2 z.c
        }
        if (s < best) { best = s; bi = k; }
    }
    #pragma unroll
    for (int off = 16; off; off >>= 1) {
        float ov = __shfl_down_sync(0xffffffffu, best, off);
        int   oi = __shfl_down_sync(0xffffffffu, bi,   off);
        if (ov < best || (ov == best && oi < bi)) { best = ov; bi = oi; }
    }
    bi = __shfl_sync(0xffffffffu, bi, 0);

    if (lane == 0) ids_out[n] = (float)bi;
    const float* c = cb + bi * ZCH;
    float* ekb = ek + (long)b * ZCH * 1024 + hw;
    ekb[(long)lane * 1024]        = c[lane];
    ekb[(long)(lane + 32) * 1024] = c[lane + 32];
}

// ---------------- t1 subpixel weight prep ----------------
// wsub[pz=2p+q][oc][ic][ky'][kx'] = t1_w[ic][oc][3 - p - 2ky'][3 - q - 2kx']
__global__ void wt_kernel(const float* __restrict__ w, float* __restrict__ wf)
{
    int i = blockIdx.x * blockDim.x + threadIdx.x;
    const int total = 4 * HIDC * HIDC * 4;
    if (i >= total) return;
    int kx = i & 1, ky = (i >> 1) & 1;
    int r1 = i >> 2;
    int ic = r1 & (HIDC - 1);
    int r2 = r1 >> 8;
    int oc = r2 & (HIDC - 1);
    int pz = r2 >> 8;
    int p = pz >> 1, q = pz & 1;
    wf[i] = w[((long)(ic * HIDC + oc) << 4) + (3 - p - 2 * ky) * 4 + (3 - q - 2 * kx)];
}

// ---------------- t2: direct transposed conv 256->3, k4 s2 p1, fused sigmoid ----------------
__global__ __launch_bounds__(128) void t2_kernel(
    const float* __restrict__ in,   // (8,256,64,64)
    const float* __restrict__ w,    // t2_w (256,3,4,4)
    const float* __restrict__ bias, // (3,)
    float* __restrict__ out)        // (8,3,128,128)
{
    __shared__ float ws[HIDC][3][8];
    const int oy   = blockIdx.x;
    const int bimg = blockIdx.y;
    const int ox   = threadIdx.x;
    const int p = oy & 1;

    for (int idx = threadIdx.x; idx < HIDC * 3 * 8; idx += 128) {
        int ic = idx / 24;
        int r  = idx - ic * 24;
        int oc = r >> 3;
        int t  = r & 7;
        int kyi = t >> 2, kx = t & 3;
        int ky = p + 2 * kyi;
        ws[ic][oc][t] = w[((long)(ic * 3 + oc) << 4) + (3 - ky) * 4 + (3 - kx)];
    }
    __syncthreads();

    const int q = ox & 1;
    const int iy0 = (oy + p - 2) >> 1;
    const int iy1 = (oy + p) >> 1;
    const int ix0 = (ox + q - 2) >> 1;
    const int ix1 = (ox + q) >> 1;
    const bool vy0 = (iy0 >= 0), vy1 = (iy1 < 64);
    const bool vx0 = (ix0 >= 0), vx1 = (ix1 < 64);

    const float* inb = in + (long)bimg * HIDC * 4096;
    float acc0 = 0.f, acc1 = 0.f, acc2 = 0.f;
    for (int ic = 0; ic < HIDC; ic++) {
        const float* pl = inb + ic * 4096;
        float v00 = (vy0 && vx0) ? pl[iy0 * 64 + ix0] : 0.f;
        float v01 = (vy0 && vx1) ? pl[iy0 * 64 + ix1] : 0.f;
        float v10 = (vy1 && vx0) ? pl[iy1 * 64 + ix0] : 0.f;
        float v11 = (vy1 && vx1) ? pl[iy1 * 64 + ix1] : 0.f;
        const float* wr0 = ws[ic][0];
        const float* wr1 = ws[ic][1];
        const float* wr2 = ws[ic][2];
        acc0 = fmaf(v00, wr0[q], fmaf(v01, wr0[q+2], fmaf(v10, wr0[4+q], fmaf(v11, wr0[4+q+2], acc0))));
        acc1 = fmaf(v00, wr1[q], fmaf(v01, wr1[q+2], fmaf(v10, wr1[4+q], fmaf(v11, wr1[4+q+2], acc1))));
        acc2 = fmaf(v00, wr2[q], fmaf(v01, wr2[q+2], fmaf(v10, wr2[4+q], fmaf(v11, wr2[4+q+2], acc2))));
    }
    long ob = ((long)bimg * 3) * 16384 + (long)oy * 128 + ox;
    float s0 = acc0 + bias[0], s1 = acc1 + bias[1], s2 = acc2 + bias[2];
    out[ob]           = 1.f / (1.f + expf(-s0));
    out[ob + 16384]   = 1.f / (1.f + expf(-s1));
    out[ob + 32768]   = 1.f / (1.f + expf(-s2));
}

// ---------------- host ----------------
extern "C" void kernel_launch(void* const* d_in, const int* in_sizes, int n_in,
                              void* d_out, int out_size)
{
    const float* x      = (const float*)d_in[0];
    const float* c1_w   = (const float*)d_in[1];
    const float* c1_b   = (const float*)d_in[2];
    const float* c2_w   = (const float*)d_in[3];
    const float* c2_b   = (const float*)d_in[4];
    const float* r0_w3  = (const float*)d_in[5];
    const float* r0_b3  = (const float*)d_in[6];
    const float* r0_w1  = (const float*)d_in[7];
    const float* r0_b1  = (const float*)d_in[8];
    const float* r1_w3  = (const float*)d_in[9];
    const float* r1_b3  = (const float*)d_in[10];
    const float* r1_w1  = (const float*)d_in[11];
    const float* r1_b1  = (const float*)d_in[12];
    const float* to_z_w = (const float*)d_in[13];
    const float* to_z_b = (const float*)d_in[14];
    const float* codebk = (const float*)d_in[15];
    const float* fz_w   = (const float*)d_in[16];
    const float* fz_b   = (const float*)d_in[17];
    const float* t1_w   = (const float*)d_in[18];
    const float* t1_b   = (const float*)d_in[19];
    const float* t2_w   = (const float*)d_in[20];
    const float* t2_b   = (const float*)d_in[21];
    float* out = (float*)d_out;

    // output layout: [out 393216][z_e 524288][e_k 524288][ids 8192]
    const long ZE_OFF  = 393216;
    const long EK_OFF  = 917504;
    const long IDS_OFF = 1441792;

    float *h1, *h2a, *h2b, *rr, *d1, *d2, *wt1;
    cudaGetSymbolAddress((void**)&h1,  g_h1);
    cudaGetSymbolAddress((void**)&h2a, g_h2a);
    cudaGetSymbolAddress((void**)&h2b, g_h2b);
    cudaGetSymbolAddress((void**)&rr,  g_rr);
    cudaGetSymbolAddress((void**)&d1,  g_d1);
    cudaGetSymbolAddress((void**)&d2,  g_d2);
    cudaGetSymbolAddress((void**)&wt1, g_wt1);

    // weight prep for t1 (independent; launch early)
    wt_kernel<<<(4 * HIDC * HIDC * 4 + 255) / 256, 256>>>(t1_w, wt1);

    // ---- encoder ----
    // c1: 3->256, k4 s2 p1, relu. N = 8*64*64 = 32768
    conv_gemm<4, 4, 128, 8, false, true><<<dim3(256, 2), 256>>>(
        c1_w, x, c1_b, nullptr, h1,
        3, 128, 128, 256, 64, 64, 2, 1, 48, 1, 0, 64, 64);

    // c2: 256->256, k4 s2 p1, relu. N = 8192
    conv_gemm<4, 4, 128, 8, false, true><<<dim3(64, 2), 256>>>(
        c2_w, h1, c2_b, nullptr, h2a,
        256, 64, 64, 256, 32, 32, 2, 1, 4096, 1, 0, 32, 32);

    // res block 0
    conv_gemm<3, 3, 128, 8, false, true><<<dim3(64, 2), 256>>>(
        r0_w3, h2a, r0_b3, nullptr, rr,
        256, 32, 32, 256, 32, 32, 1, 1, 2304, 0, 1, 32, 32);
    conv_gemm<1, 1, 128, 8, false, true><<<dim3(64, 2), 256>>>(
        r0_w1, rr, r0_b1, h2a, h2b,
        256, 32, 32, 256, 32, 32, 1, 0, 256, 0, 1, 32, 32);
    // res block 1
    conv_gemm<3, 3, 128, 8, false, true><<<dim3(64, 2), 256>>>(
        r1_w3, h2b, r1_b3, nullptr, rr,
        256, 32, 32, 256, 32, 32, 1, 1, 2304, 0, 1, 32, 32);
    conv_gemm<1, 1, 128, 8, false, true><<<dim3(64, 2), 256>>>(
        r1_w1, rr, r1_b1, h2b, h2a,
        256, 32, 32, 256, 32, 32, 1, 0, 256, 0, 1, 32, 32);

    // to_z: 256->64, 1x1 -> z_e
    conv_gemm<1, 1, 64, 4, false, true><<<dim3(64, 1), 256>>>(
        to_z_w, h2a, to_z_b, nullptr, out + ZE_OFF,
        256, 32, 32, 64, 32, 32, 1, 0, 256, 0, 0, 32, 32);

    // VQ: ids + e_k
    vq_kernel<<<2048, 128>>>(out + ZE_OFF, codebk, out + EK_OFF, out + IDS_OFF);

    // from_z: 64->256, 1x1, relu
    conv_gemm<1, 1, 128, 8, false, true><<<dim3(64, 2), 256>>>(
        fz_w, out + EK_OFF, fz_b, nullptr, d1,
        64, 32, 32, 256, 32, 32, 1, 0, 64, 1, 0, 32, 32);

    // t1: convT 256->256 k4 s2 p1 as 4 subpixel 2x2 convs (grid.z = parity), relu
    conv_gemm<2, 2, 128, 8, true, false><<<dim3(64, 2, 4), 256>>>(
        wt1, d1, t1_b, nullptr, d2,
        256, 32, 32, 256, 32, 32, 1, 0, 1024, 1, 0, 64, 64);

    // t2: direct transposed conv 256->3 + sigmoid
    t2_kernel<<<dim3(128, BATCH), 128>>>(d2, t2_w, t2_b, out);
}

// round 6
// speedup vs baseline: 1.6282x; 1.6282x over previous
#include <cuda_runtime.h>
#include <math.h>
#include <float.h>

#define BATCH 8
#define HIDC  256
#define ZCH   64
#define KCODE 512

// ---------------- scratch (device globals; no allocation allowed) ----------------
__device__ float g_h1 [BATCH * HIDC * 64 * 64];  // after c1
__device__ float g_h2a[BATCH * HIDC * 32 * 32];  // ping
__device__ float g_h2b[BATCH * HIDC * 32 * 32];  // pong
__device__ float g_rr [BATCH * HIDC * 32 * 32];  // residual intermediate
__device__ float g_d1 [BATCH * HIDC * 32 * 32];  // decoder stage 1
__device__ float g_d2 [BATCH * HIDC * 64 * 64];  // decoder stage 2
__device__ float g_wt1[4 * HIDC * HIDC * 4];     // subpixel-decomposed t1 weights

// packed fp32x2 FMA (Blackwell): d = a * b + d, elementwise on 2 packed f32
__device__ __forceinline__ void fma2(unsigned long long& d,
                                     unsigned long long a,
                                     unsigned long long b)
{
    asm("fma.rn.f32x2 %0, %1, %2, %0;" : "+l"(d) : "l"(a), "l"(b));
}
__device__ __forceinline__ unsigned long long dup2(float v)
{
    unsigned long long r;
    asm("mov.b64 %0, {%1, %1};" : "=l"(r) : "f"(v));
    return r;
}

// =======================================================================
// Implicit-GEMM conv, double-buffered smem, f32x2 packed math.
//   C[M=Cout][N=B*Hout*Wout] = A[M][K] * B(gathered)[K][N]
// BN=128, BK=8 fixed. BMv=64/TM=4 for all big layers: grid = Cout/64 * N/128
// blocks. CRITICAL (round-5 lesson): the 256-channel layers need >=256 CTAs
// so SMs can hold 2 CTAs; BM=128 capped the grid at 128 (< 148 SMs) and
// single-CTA barriers starved issue at ~32%.
// SUBPIX: 2x2 subpixel conv implementing convT(k4,s2,p1); blockIdx.z = parity.
// =======================================================================
template<int KH, int KW, int BMv, int TM, bool SUBPIX, bool VST>
__global__ __launch_bounds__(256, 2) void conv_gemm(
    const float* __restrict__ A, const float* __restrict__ in,
    const float* __restrict__ bias, const float* __restrict__ res,
    float* __restrict__ out,
    int Cin, int Hin, int Win, int Cout, int Hout, int Wout,
    int stride, int pad, int K, int act, int inRelu,
    int Hfull, int Wfull)
{
    constexpr int BN = 128, BK = 8, TN = 8;
    constexpr int KHW = KH * KW;
    constexpr int TP = TM / 2;                 // M-pairs per thread
    __shared__ float As[2][BK][BMv];
    __shared__ float Bs[2][BK][BN];

    const int tid = threadIdx.x;
    const int m0 = blockIdx.y * BMv;
    const int n0 = blockIdx.x * BN;
    const int HW = Hout * Wout;

    int par_y = 0, par_x = 0;
    const float* Ab = A;
    if (SUBPIX) {
        int pz = blockIdx.z;
        par_y = pz >> 1; par_x = pz & 1;
        Ab = A + (long)pz * Cout * K;
    }

    // ---- B gather mapping: fixed n per thread, 4 consecutive k ----
    const int bn = tid & (BN - 1);
    const int bk = (tid >> 7) << 2;
    const int n  = n0 + bn;
    const int bimg = n / HW;
    const int hw   = n - bimg * HW;
    const int oy   = hw / Wout;
    const int ox   = hw - oy * Wout;
    const float* inb = in + (long)bimg * Cin * Hin * Win;
    int iy0, ix0;
    if (SUBPIX) { iy0 = oy - (1 - par_y); ix0 = ox - (1 - par_x); }
    else        { iy0 = oy * stride - pad; ix0 = ox * stride - pad; }

    // ---- A load mapping: one float4 per (active) thread per tile ----
    constexpr int NA4 = BMv * BK / 4;     // 256 or 128
    const int am = tid >> 1;
    const int ak = (tid & 1) << 2;
    const bool aload = (NA4 == 256) || (tid < 128);
    const float* Arow = aload ? (Ab + (long)(m0 + am) * K + ak) : Ab;

    // ---- compute mapping ----
    const int rm = (tid & 15) * TM;
    const int rn = (tid >> 4) * TN;
    unsigned long long acc2[TP][TN];
    #pragma unroll
    for (int i = 0; i < TP; i++)
        #pragma unroll
        for (int j = 0; j < TN; j++) acc2[i][j] = 0ull;

    auto gatherB = [&](int k0, float* bv) {
        #pragma unroll
        for (int i = 0; i < 4; i++) {
            int k  = k0 + bk + i;
            int ic = k / KHW;
            int rr = k - ic * KHW;
            int ky = rr / KW;
            int kx = rr - ky * KW;
            int iy = iy0 + ky;
            int ix = ix0 + kx;
            float v = 0.f;
            if ((unsigned)iy < (unsigned)Hin && (unsigned)ix < (unsigned)Win)
                v = inb[(ic * Hin + iy) * Win + ix];
            if (inRelu) v = fmaxf(v, 0.f);
            bv[i] = v;
        }
    };

    const int nt = K / BK;
    float4 av;
    float  bv[4];

    // preload tile 0
    if (aload) av = *reinterpret_cast<const float4*>(Arow);
    gatherB(0, bv);
    if (aload) {
        As[0][ak + 0][am] = av.x; As[0][ak + 1][am] = av.y;
        As[0][ak + 2][am] = av.z; As[0][ak + 3][am] = av.w;
    }
    #pragma unroll
    for (int i = 0; i < 4; i++) Bs[0][bk + i][bn] = bv[i];
    __syncthreads();

    int cur = 0;
    for (int t = 0; t < nt; t++) {
        if (t + 1 < nt) {
            int k0n = (t + 1) * BK;
            if (aload) av = *reinterpret_cast<const float4*>(Arow + k0n);
            gatherB(k0n, bv);
        }
        #pragma unroll
        for (int kk = 0; kk < BK; kk++) {
            // A-side: TP packed pairs along M, free from 64-bit smem reads
            unsigned long long ap[TP];
            {
                ulonglong2 u0 = *reinterpret_cast<const ulonglong2*>(&As[cur][kk][rm]);
                ap[0] = u0.x; ap[1] = u0.y;
                if (TP == 4) {
                    ulonglong2 u1 = *reinterpret_cast<const ulonglong2*>(&As[cur][kk][rm + 4]);
                    ap[2] = u1.x; ap[3] = u1.y;
                }
            }
            float b[TN];
            *reinterpret_cast<float4*>(&b[0]) = *reinterpret_cast<const float4*>(&Bs[cur][kk][rn]);
            *reinterpret_cast<float4*>(&b[4]) = *reinterpret_cast<const float4*>(&Bs[cur][kk][rn + 4]);
            #pragma unroll
            for (int j = 0; j < TN; j++) {
                unsigned long long bd = dup2(b[j]);
                #pragma unroll
                for (int i = 0; i < TP; i++)
                    fma2(acc2[i][j], ap[i], bd);
            }
        }
        if (t + 1 < nt) {
            int nx = cur ^ 1;
            if (aload) {
                As[nx][ak + 0][am] = av.x; As[nx][ak + 1][am] = av.y;
                As[nx][ak + 2][am] = av.z; As[nx][ak + 3][am] = av.w;
            }
            #pragma unroll
            for (int i = 0; i < 4; i++) Bs[nx][bk + i][bn] = bv[i];
            __syncthreads();
            cur = nx;
        }
    }

    // ---- epilogue ----
    const int nb  = n0 + rn;
    const int b2  = nb / HW;                 // same image for all TN columns
    const int hwb = nb - b2 * HW;
    const int eoy = hwb / Wout;
    const int eox = hwb - eoy * Wout;        // row-constant: eox+TN-1 < Wout
    const long HWf = (long)Hfull * Wfull;
    const long base = (long)b2 * Cout * HWf;

    #pragma unroll
    for (int i = 0; i < TM; i++) {
        const int oc = m0 + rm + i;
        const float bvs = bias[oc];
        if (VST && !SUBPIX) {
            long idx = base + (long)oc * HWf + hwb;
            #pragma unroll
            for (int j = 0; j < TN; j += 4) {
                float2 p0 = *reinterpret_cast<const float2*>(&acc2[i >> 1][j + 0]);
                float2 p1 = *reinterpret_cast<const float2*>(&acc2[i >> 1][j + 1]);
                float2 p2 = *reinterpret_cast<const float2*>(&acc2[i >> 1][j + 2]);
                float2 p3 = *reinterpret_cast<const float2*>(&acc2[i >> 1][j + 3]);
                float4 v;
                v.x = ((i & 1) ? p0.y : p0.x) + bvs;
                v.y = ((i & 1) ? p1.y : p1.x) + bvs;
                v.z = ((i & 1) ? p2.y : p2.x) + bvs;
                v.w = ((i & 1) ? p3.y : p3.x) + bvs;
                if (res) {
                    float4 r = *reinterpret_cast<const float4*>(res + idx + j);
                    v.x += r.x; v.y += r.y; v.z += r.z; v.w += r.w;
                }
                if (act == 1) {
                    v.x = fmaxf(v.x, 0.f); v.y = fmaxf(v.y, 0.f);
                    v.z = fmaxf(v.z, 0.f); v.w = fmaxf(v.w, 0.f);
                }
                *reinterpret_cast<float4*>(out + idx + j) = v;
            }
        } else {
            #pragma unroll
            for (int j = 0; j < TN; j++) {
                float2 p = *reinterpret_cast<const float2*>(&acc2[i >> 1][j]);
                float v = ((i & 1) ? p.y : p.x) + bvs;
                if (act == 1) v = fmaxf(v, 0.f);
                int fy, fx;
                if (SUBPIX) { fy = 2 * eoy + par_y; fx = 2 * (eox + j) + par_x; }
                else        { fy = eoy;             fx = eox + j; }
                out[base + (long)oc * HWf + (long)fy * Wfull + fx] = v;
            }
        }
    }
}

// ---------------- VQ: one warp per z-vector ----------------
__global__ __launch_bounds__(128) void vq_kernel(
    const float* __restrict__ z, const float* __restrict__ cb,
    float* __restrict__ ek, float* __restrict__ ids_out)
{
    const int warp = threadIdx.x >> 5;
    const int lane = threadIdx.x & 31;
    const int n = blockIdx.x * 4 + warp;         // [0, 8192)
    const int b  = n >> 10;
    const int hw = n & 1023;

    __shared__ float zs[4][ZCH];
    const float* zb = z + (long)b * ZCH * 1024 + hw;
    zs[warp][lane]      = zb[(long)lane * 1024];
    zs[warp][lane + 32] = zb[(long)(lane + 32) * 1024];
    __syncwarp();

    float best = FLT_MAX;
    int bi = 0;
    for (int k = lane; k < KCODE; k += 32) {
        const float* c = cb + k * ZCH;
        float s = 0.f;
        #pragma unroll 16
        for (int ci = 0; ci < ZCH; ci++) {
            float cv = c[ci];
            s = fmaf(cv, cv - 2.f * zs[warp][ci], s);   // |c|^2 - 2 z.c
        }
        if (s < best) { best = s; bi = k; }
    }
    #pragma unroll
    for (int off = 16; off; off >>= 1) {
        float ov = __shfl_down_sync(0xffffffffu, best, off);
        int   oi = __shfl_down_sync(0xffffffffu, bi,   off);
        if (ov < best || (ov == best && oi < bi)) { best = ov; bi = oi; }
    }
    bi = __shfl_sync(0xffffffffu, bi, 0);

    if (lane == 0) ids_out[n] = (float)bi;
    const float* c = cb + bi * ZCH;
    float* ekb = ek + (long)b * ZCH * 1024 + hw;
    ekb[(long)lane * 1024]        = c[lane];
    ekb[(long)(lane + 32) * 1024] = c[lane + 32];
}

// ---------------- t1 subpixel weight prep ----------------
// wsub[pz=2p+q][oc][ic][ky'][kx'] = t1_w[ic][oc][3 - p - 2ky'][3 - q - 2kx']
__global__ void wt_kernel(const float* __restrict__ w, float* __restrict__ wf)
{
    int i = blockIdx.x * blockDim.x + threadIdx.x;
    const int total = 4 * HIDC * HIDC * 4;
    if (i >= total) return;
    int kx = i & 1, ky = (i >> 1) & 1;
    int r1 = i >> 2;
    int ic = r1 & (HIDC - 1);
    int r2 = r1 >> 8;
    int oc = r2 & (HIDC - 1);
    int pz = r2 >> 8;
    int p = pz >> 1, q = pz & 1;
    wf[i] = w[((long)(ic * HIDC + oc) << 4) + (3 - p - 2 * ky) * 4 + (3 - q - 2 * kx)];
}

// ---------------- t2: direct transposed conv 256->3, k4 s2 p1, fused sigmoid ----------------
__global__ __launch_bounds__(128) void t2_kernel(
    const float* __restrict__ in,   // (8,256,64,64)
    const float* __restrict__ w,    // t2_w (256,3,4,4)
    const float* __restrict__ bias, // (3,)
    float* __restrict__ out)        // (8,3,128,128)
{
    __shared__ float ws[HIDC][3][8];
    const int oy   = blockIdx.x;
    const int bimg = blockIdx.y;
    const int ox   = threadIdx.x;
    const int p = oy & 1;

    for (int idx = threadIdx.x; idx < HIDC * 3 * 8; idx += 128) {
        int ic = idx / 24;
        int r  = idx - ic * 24;
        int oc = r >> 3;
        int t  = r & 7;
        int kyi = t >> 2, kx = t & 3;
        int ky = p + 2 * kyi;
        ws[ic][oc][t] = w[((long)(ic * 3 + oc) << 4) + (3 - ky) * 4 + (3 - kx)];
    }
    __syncthreads();

    const int q = ox & 1;
    const int iy0 = (oy + p - 2) >> 1;
    const int iy1 = (oy + p) >> 1;
    const int ix0 = (ox + q - 2) >> 1;
    const int ix1 = (ox + q) >> 1;
    const bool vy0 = (iy0 >= 0), vy1 = (iy1 < 64);
    const bool vx0 = (ix0 >= 0), vx1 = (ix1 < 64);

    const float* inb = in + (long)bimg * HIDC * 4096;
    float acc0 = 0.f, acc1 = 0.f, acc2 = 0.f;
    for (int ic = 0; ic < HIDC; ic++) {
        const float* pl = inb + ic * 4096;
        float v00 = (vy0 && vx0) ? pl[iy0 * 64 + ix0] : 0.f;
        float v01 = (vy0 && vx1) ? pl[iy0 * 64 + ix1] : 0.f;
        float v10 = (vy1 && vx0) ? pl[iy1 * 64 + ix0] : 0.f;
        float v11 = (vy1 && vx1) ? pl[iy1 * 64 + ix1] : 0.f;
        const float* wr0 = ws[ic][0];
        const float* wr1 = ws[ic][1];
        const float* wr2 = ws[ic][2];
        acc0 = fmaf(v00, wr0[q], fmaf(v01, wr0[q+2], fmaf(v10, wr0[4+q], fmaf(v11, wr0[4+q+2], acc0))));
        acc1 = fmaf(v00, wr1[q], fmaf(v01, wr1[q+2], fmaf(v10, wr1[4+q], fmaf(v11, wr1[4+q+2], acc1))));
        acc2 = fmaf(v00, wr2[q], fmaf(v01, wr2[q+2], fmaf(v10, wr2[4+q], fmaf(v11, wr2[4+q+2], acc2))));
    }
    long ob = ((long)bimg * 3) * 16384 + (long)oy * 128 + ox;
    float s0 = acc0 + bias[0], s1 = acc1 + bias[1], s2 = acc2 + bias[2];
    out[ob]           = 1.f / (1.f + expf(-s0));
    out[ob + 16384]   = 1.f / (1.f + expf(-s1));
    out[ob + 32768]   = 1.f / (1.f + expf(-s2));
}

// ---------------- host ----------------
extern "C" void kernel_launch(void* const* d_in, const int* in_sizes, int n_in,
                              void* d_out, int out_size)
{
    const float* x      = (const float*)d_in[0];
    const float* c1_w   = (const float*)d_in[1];
    const float* c1_b   = (const float*)d_in[2];
    const float* c2_w   = (const float*)d_in[3];
    const float* c2_b   = (const float*)d_in[4];
    const float* r0_w3  = (const float*)d_in[5];
    const float* r0_b3  = (const float*)d_in[6];
    const float* r0_w1  = (const float*)d_in[7];
    const float* r0_b1  = (const float*)d_in[8];
    const float* r1_w3  = (const float*)d_in[9];
    const float* r1_b3  = (const float*)d_in[10];
    const float* r1_w1  = (const float*)d_in[11];
    const float* r1_b1  = (const float*)d_in[12];
    const float* to_z_w = (const float*)d_in[13];
    const float* to_z_b = (const float*)d_in[14];
    const float* codebk = (const float*)d_in[15];
    const float* fz_w   = (const float*)d_in[16];
    const float* fz_b   = (const float*)d_in[17];
    const float* t1_w   = (const float*)d_in[18];
    const float* t1_b   = (const float*)d_in[19];
    const float* t2_w   = (const float*)d_in[20];
    const float* t2_b   = (const float*)d_in[21];
    float* out = (float*)d_out;

    // output layout: [out 393216][z_e 524288][e_k 524288][ids 8192]
    const long ZE_OFF  = 393216;
    const long EK_OFF  = 917504;
    const long IDS_OFF = 1441792;

    float *h1, *h2a, *h2b, *rr, *d1, *d2, *wt1;
    cudaGetSymbolAddress((void**)&h1,  g_h1);
    cudaGetSymbolAddress((void**)&h2a, g_h2a);
    cudaGetSymbolAddress((void**)&h2b, g_h2b);
    cudaGetSymbolAddress((void**)&rr,  g_rr);
    cudaGetSymbolAddress((void**)&d1,  g_d1);
    cudaGetSymbolAddress((void**)&d2,  g_d2);
    cudaGetSymbolAddress((void**)&wt1, g_wt1);

    // weight prep for t1 (independent; launch early)
    wt_kernel<<<(4 * HIDC * HIDC * 4 + 255) / 256, 256>>>(t1_w, wt1);

    // ---- encoder ----
    // c1: 3->256, k4 s2 p1, relu. N = 8*64*64 = 32768 -> grid 256x4 = 1024 CTAs
    conv_gemm<4, 4, 64, 4, false, true><<<dim3(256, 4), 256>>>(
        c1_w, x, c1_b, nullptr, h1,
        3, 128, 128, 256, 64, 64, 2, 1, 48, 1, 0, 64, 64);

    // c2: 256->256, k4 s2 p1, relu. N = 8192 -> grid 64x4 = 256 CTAs
    conv_gemm<4, 4, 64, 4, false, true><<<dim3(64, 4), 256>>>(
        c2_w, h1, c2_b, nullptr, h2a,
        256, 64, 64, 256, 32, 32, 2, 1, 4096, 1, 0, 32, 32);

    // res block 0
    conv_gemm<3, 3, 64, 4, false, true><<<dim3(64, 4), 256>>>(
        r0_w3, h2a, r0_b3, nullptr, rr,
        256, 32, 32, 256, 32, 32, 1, 1, 2304, 0, 1, 32, 32);
    conv_gemm<1, 1, 64, 4, false, true><<<dim3(64, 4), 256>>>(
        r0_w1, rr, r0_b1, h2a, h2b,
        256, 32, 32, 256, 32, 32, 1, 0, 256, 0, 1, 32, 32);
    // res block 1
    conv_gemm<3, 3, 64, 4, false, true><<<dim3(64, 4), 256>>>(
        r1_w3, h2b, r1_b3, nullptr, rr,
        256, 32, 32, 256, 32, 32, 1, 1, 2304, 0, 1, 32, 32);
    conv_gemm<1, 1, 64, 4, false, true><<<dim3(64, 4), 256>>>(
        r1_w1, rr, r1_b1, h2b, h2a,
        256, 32, 32, 256, 32, 32, 1, 0, 256, 0, 1, 32, 32);

    // to_z: 256->64, 1x1 -> z_e
    conv_gemm<1, 1, 64, 4, false, true><<<dim3(64, 1), 256>>>(
        to_z_w, h2a, to_z_b, nullptr, out + ZE_OFF,
        256, 32, 32, 64, 32, 32, 1, 0, 256, 0, 0, 32, 32);

    // VQ: ids + e_k
    vq_kernel<<<2048, 128>>>(out + ZE_OFF, codebk, out + EK_OFF, out + IDS_OFF);

    // from_z: 64->256, 1x1, relu
    conv_gemm<1, 1, 64, 4, false, true><<<dim3(64, 4), 256>>>(
        fz_w, out + EK_OFF, fz_b, nullptr, d1,
        64, 32, 32, 256, 32, 32, 1, 0, 64, 1, 0, 32, 32);

    // t1: convT 256->256 k4 s2 p1 as 4 subpixel 2x2 convs (grid.z = parity), relu
    conv_gemm<2, 2, 64, 4, true, false><<<dim3(64, 4, 4), 256>>>(
        wt1, d1, t1_b, nullptr, d2,
        256, 32, 32, 256, 32, 32, 1, 0, 1024, 1, 0, 64, 64);

    // t2: direct transposed conv 256->3 + sigmoid
    t2_kernel<<<dim3(128, BATCH), 128>>>(d2, t2_w, t2_b, out);
}